// round 14
// baseline (speedup 1.0000x reference)
#include <cuda_runtime.h>
#include <cuda_bf16.h>
#include <cstdint>

#define BB 128
#define TT 4096
#define NN 32
#define FULL 0xffffffffu
#define KSEG 64                 // segments per chain
#define SEGLEN (TT / KSEG)      // 64
#define WARM 8                  // warm-up steps (Hilbert contraction burn-in)
#define WPB 8                   // warps per block in fb
#define NWORK_MAX (2 * BB * KSEG)
#define NCHUNK 16
#define CHUNK (TT / NCHUNK)

// bf16 tapes for scaled forward/backward messages (scale cancels in ratios).
__device__ __nv_bfloat16 g_a[(size_t)BB * TT * NN];
__device__ __nv_bfloat16 g_b[(size_t)BB * TT * NN];
__device__ float g_partial[BB][NCHUNK];
__device__ int   g_arrive[BB];        // combine last-block-done counters
__device__ int   g_work[NWORK_MAX];   // packed (b<<7)|(dir<<6)|seg
__device__ int   g_nwork;

__device__ __forceinline__ __nv_bfloat162 asbf2(unsigned int u) {
    __nv_bfloat162 h;
    *reinterpret_cast<unsigned int*>(&h) = u;
    return h;
}

// Matvec step, bf16 state end-to-end: broadcast v via STS.16 into a 64B smem
// row, read back as 4x LDS.128 (16 bf16x2 operands), 16 HFMA2 against the
// bf16x2-packed E, 3 HADD2 + 1 HADD tree. Returns the raw dot s (bf16); the
// renorm factor rcp(v0) is returned separately (fp32, computed off-path).
__device__ __forceinline__ __nv_bfloat16 matvec_bf16(__nv_bfloat16 v,
                                                     unsigned int srow,
                                                     int lane,
                                                     const __nv_bfloat162* E2,
                                                     float& rout)
{
    unsigned short vs;
    *reinterpret_cast<__nv_bfloat16*>(&vs) = v;
    asm volatile("st.shared.u16 [%0], %1;"
                 :: "r"(srow + 2u * (unsigned)lane), "h"(vs) : "memory");
    __syncwarp();
    unsigned int w0, w1, w2, w3, w4, w5, w6, w7, w8, w9, wa, wb, wc, wd, we, wf;
    asm volatile("ld.shared.v4.u32 {%0,%1,%2,%3}, [%4];"
                 : "=r"(w0), "=r"(w1), "=r"(w2), "=r"(w3) : "r"(srow));
    asm volatile("ld.shared.v4.u32 {%0,%1,%2,%3}, [%4];"
                 : "=r"(w4), "=r"(w5), "=r"(w6), "=r"(w7) : "r"(srow + 16u));
    asm volatile("ld.shared.v4.u32 {%0,%1,%2,%3}, [%4];"
                 : "=r"(w8), "=r"(w9), "=r"(wa), "=r"(wb) : "r"(srow + 32u));
    asm volatile("ld.shared.v4.u32 {%0,%1,%2,%3}, [%4];"
                 : "=r"(wc), "=r"(wd), "=r"(we), "=r"(wf) : "r"(srow + 48u));

    rout = __frcp_rn(__low2float(asbf2(w0)));     // renorm, off critical path

    __nv_bfloat162 z = __floats2bfloat162_rn(0.f, 0.f);
    __nv_bfloat162 acc0 = z, acc1 = z, acc2 = z, acc3 = z;
    acc0 = __hfma2(asbf2(w0), E2[0],  acc0);
    acc1 = __hfma2(asbf2(w1), E2[1],  acc1);
    acc2 = __hfma2(asbf2(w2), E2[2],  acc2);
    acc3 = __hfma2(asbf2(w3), E2[3],  acc3);
    acc0 = __hfma2(asbf2(w4), E2[4],  acc0);
    acc1 = __hfma2(asbf2(w5), E2[5],  acc1);
    acc2 = __hfma2(asbf2(w6), E2[6],  acc2);
    acc3 = __hfma2(asbf2(w7), E2[7],  acc3);
    acc0 = __hfma2(asbf2(w8), E2[8],  acc0);
    acc1 = __hfma2(asbf2(w9), E2[9],  acc1);
    acc2 = __hfma2(asbf2(wa), E2[10], acc2);
    acc3 = __hfma2(asbf2(wb), E2[11], acc3);
    acc0 = __hfma2(asbf2(wc), E2[12], acc0);
    acc1 = __hfma2(asbf2(wd), E2[13], acc1);
    acc2 = __hfma2(asbf2(we), E2[14], acc2);
    acc3 = __hfma2(asbf2(wf), E2[15], acc3);

    __nv_bfloat162 tsum = __hadd2(__hadd2(acc0, acc1), __hadd2(acc2, acc3));
    return __hadd(__low2bfloat16(tsum), __high2bfloat16(tsum));
}

// ---------------------------------------------------------------------------
// Kernel 0: build the dense work list of active (batch, dir, seg) entries.
// 1024 threads: per-batch counts, single-thread scan of 128 ints, then
// grid-strided parallel entry writes. Also resets combine arrival counters.
// ---------------------------------------------------------------------------
__global__ void __launch_bounds__(1024)
plan_kernel(const int* __restrict__ lengths)
{
    __shared__ int snseg[BB];
    __shared__ int soff[BB];
    const int tid = threadIdx.x;
    if (tid < BB) {
        g_arrive[tid] = 0;
        int len = lengths[tid];
        snseg[tid] = (len + SEGLEN - 1) / SEGLEN;
    }
    __syncthreads();
    if (tid == 0) {
        int acc = 0;
        #pragma unroll 4
        for (int i = 0; i < BB; i++) { soff[i] = acc; acc += 2 * snseg[i]; }
        g_nwork = acc;
    }
    __syncthreads();
    for (int idx = tid; idx < BB * 2 * KSEG; idx += 1024) {
        int b = idx >> 7;            // / (2*KSEG)
        int j = idx & (2 * KSEG - 1);
        if (j < 2 * snseg[b]) {
            int s   = j >> 1;
            int dir = j & 1;
            g_work[soff[b] + j] = (b << 7) | (dir << 6) | s;
        }
    }
}

// ---------------------------------------------------------------------------
// Kernel 1: segmented forward/backward recursions over the compacted work
// list; one warp per entry, lane = state. Probability-domain recursion with
// per-step rescale (scale cancels in marginal ratios -> no log/lse).
// Mid-chain segments start WARM steps early from a uniform positive vector;
// diag(P)E^T contracts direction error ~0.32x/step (Hilbert metric)
// => ~1e-4 after 8 steps (averages out in the dice sums). Boundary segments
// use the exact init. State carried in bf16; bf16(r*P) applied off-path.
// ---------------------------------------------------------------------------
__global__ void __launch_bounds__(32 * WPB)
fb_kernel(const float* __restrict__ pots,
          const int*   __restrict__ lengths,
          const float* __restrict__ trans)
{
    __shared__ __align__(16) __nv_bfloat16 buf[WPB][NN];

    const int lane = threadIdx.x & 31;
    const int w    = threadIdx.x >> 5;
    const int gw   = blockIdx.x * WPB + w;
    if (gw >= g_nwork) return;
    const int e    = g_work[gw];
    const int b    = e >> 7;
    const bool fwd = ((e >> 6) & 1) == 0;
    const int seg  = e & 63;

    const int len = lengths[b];
    const int t0  = seg * SEGLEN;                // t0 < len guaranteed by plan
    int t1 = t0 + SEGLEN; if (t1 > len) t1 = len;

    const float* pot = pots + (size_t)b * TT * NN;
    const unsigned int srow =
        (unsigned int)__cvta_generic_to_shared(&buf[w][0]);

    __nv_bfloat162 E2[16];                       // packed exp(trans) pairs

    if (fwd) {
        // pair k packs exp(trans[2k][lane]), exp(trans[2k+1][lane])
        #pragma unroll
        for (int k = 0; k < 16; k++)
            E2[k] = __floats2bfloat162_rn(__expf(trans[(2 * k)     * NN + lane]),
                                          __expf(trans[(2 * k + 1) * NN + lane]));

        __nv_bfloat16* A = g_a + (size_t)b * TT * NN;

        int tstart = t0 - WARM; if (tstart < 0) tstart = 0;
        __nv_bfloat16 a;
        if (tstart == 0) {
            a = __float2bfloat16(__expf(pot[lane]));
            if (t0 == 0) A[lane] = a;
        } else {
            a = __float2bfloat16(1.0f);
        }

        const int tmain = (t0 > tstart + 1) ? t0 : tstart + 1;  // first stored t
        const float* pp = pot + (size_t)(tstart + 1) * NN + lane;
        float pr = *pp;
        float r;

        // warm-up: t in [tstart+1, t0), no stores
        for (int t = tstart + 1; t < t0; ++t) {
            float P = __expf(pr);
            pp += NN; pr = *pp;
            __nv_bfloat16 s = matvec_bf16(a, srow, lane, E2, r);
            a = __hmul(s, __float2bfloat16(r * P));
        }
        // main: t in [tmain, t1-1) with prefetch (stays <= t1-1 <= TT-1)
        __nv_bfloat16* Ap = A + (size_t)tmain * NN + lane;
        for (int t = tmain; t < t1 - 1; ++t) {
            float P = __expf(pr);
            pp += NN; pr = *pp;
            __nv_bfloat16 s = matvec_bf16(a, srow, lane, E2, r);
            a = __hmul(s, __float2bfloat16(r * P));
            *Ap = a; Ap += NN;
        }
        // peeled final step t = t1-1 (no prefetch)
        if (t1 - 1 >= tmain) {
            float P = __expf(pr);
            __nv_bfloat16 s = matvec_bf16(a, srow, lane, E2, r);
            a = __hmul(s, __float2bfloat16(r * P));
            *Ap = a;
        }
    } else {
        // pair k packs exp(trans[lane][2k]), exp(trans[lane][2k+1])
        #pragma unroll
        for (int k = 0; k < 16; k++)
            E2[k] = __floats2bfloat162_rn(__expf(trans[lane * NN + 2 * k]),
                                          __expf(trans[lane * NN + 2 * k + 1]));

        __nv_bfloat16* Bv = g_b + (size_t)b * TT * NN;

        int tstart = t1 - 1 + WARM; if (tstart > len - 1) tstart = len - 1;
        __nv_bfloat16 bv = __float2bfloat16(1.0f);   // exact at len-1
        if (tstart < t1) Bv[(size_t)tstart * NN + lane] = bv;

        const float* pp = pot + (size_t)tstart * NN + lane;
        float pr = *pp;
        float r;
        int t = tstart;

        // warm-up: t in (t1, tstart], produce unstored b_{t-1}
        for (; t > t1; --t) {
            __nv_bfloat16 Pb = __float2bfloat16(__expf(pr));
            pp -= NN; pr = *pp;
            __nv_bfloat16 s = matvec_bf16(__hmul(bv, Pb), srow, lane, E2, r);
            bv = __hmul(s, __float2bfloat16(r));
        }
        // main: t down to t0+2 with prefetch (prefetch reads >= t0+1 >= 1)
        __nv_bfloat16* Bp = Bv + (size_t)(t - 1) * NN + lane;
        for (; t >= t0 + 2; --t) {
            __nv_bfloat16 Pb = __float2bfloat16(__expf(pr));
            pp -= NN; pr = *pp;
            __nv_bfloat16 s = matvec_bf16(__hmul(bv, Pb), srow, lane, E2, r);
            bv = __hmul(s, __float2bfloat16(r));
            *Bp = bv; Bp -= NN;
        }
        // peeled final step t = t0+1 (no prefetch; avoids reading row t0-1)
        if (t == t0 + 1) {
            __nv_bfloat16 Pb = __float2bfloat16(__expf(pr));
            __nv_bfloat16 s = matvec_bf16(__hmul(bv, Pb), srow, lane, E2, r);
            bv = __hmul(s, __float2bfloat16(r));
            *Bp = bv;
        }
    }
}

// ---------------------------------------------------------------------------
// Kernel 2: combine partials over bf16 tapes + fused finalize. grid
// (BB, NCHUNK); block (b,c) handles t in [c*CHUNK, (c+1)*CHUNK) ∩ [0,len),
// writes its partial slot, then the LAST block to arrive for batch b
// (atomic counter; fixed summation order -> deterministic) sums the NCHUNK
// partials and writes out[b].  p_t(y_t) = a_y b_y / sum_k a_k b_k.
// ---------------------------------------------------------------------------
__device__ __forceinline__ float2 bf2f(unsigned int u) {
    return __bfloat1622float2(asbf2(u));
}

__global__ void __launch_bounds__(256)
combine_kernel(const int* __restrict__ y_true,
               const int* __restrict__ lengths,
               float*     __restrict__ out)
{
    const int b   = blockIdx.x;
    const int c   = blockIdx.y;
    const int tid = threadIdx.x;
    const int len = lengths[b];

    const int t_lo = c * CHUNK;
    int t_hi = t_lo + CHUNK; if (t_hi > len) t_hi = len;

    const __nv_bfloat16* Ab = g_a + (size_t)b * TT * NN;
    const __nv_bfloat16* Bb = g_b + (size_t)b * TT * NN;
    const int* Yb = y_true + (size_t)b * TT;

    float part = 0.f;
    for (int t = t_lo + tid; t < t_hi; t += 256) {
        const uint4* A4 = reinterpret_cast<const uint4*>(Ab + (size_t)t * NN);
        const uint4* B4 = reinterpret_cast<const uint4*>(Bb + (size_t)t * NN);
        int y = Yb[t];
        float s = 0.f, py = 0.f;
        #pragma unroll
        for (int q = 0; q < 4; q++) {
            uint4 ua = __ldcs(&A4[q]);
            uint4 ub = __ldcs(&B4[q]);
            unsigned int aw[4] = {ua.x, ua.y, ua.z, ua.w};
            unsigned int bw[4] = {ub.x, ub.y, ub.z, ub.w};
            #pragma unroll
            for (int i = 0; i < 4; i++) {
                float2 fa = bf2f(aw[i]);
                float2 fb = bf2f(bw[i]);
                s = fmaf(fa.x, fb.x, s);
                s = fmaf(fa.y, fb.y, s);
                if ((y >> 1) == q * 4 + i)
                    py = (y & 1) ? fa.y * fb.y : fa.x * fb.x;
            }
        }
        part += __fdividef(py, s);
    }

    #pragma unroll
    for (int off = 16; off > 0; off >>= 1)
        part += __shfl_down_sync(FULL, part, off);

    __shared__ float red[8];
    __shared__ int last;
    if ((tid & 31) == 0) red[tid >> 5] = part;
    __syncthreads();
    if (tid == 0) {
        float s = 0.f;
        #pragma unroll
        for (int w2 = 0; w2 < 8; w2++) s += red[w2];
        g_partial[b][c] = s;
        __threadfence();
        int prev = atomicAdd(&g_arrive[b], 1);
        last = (prev == NCHUNK - 1) ? 1 : 0;
    }
    __syncthreads();
    if (last && tid == 0) {
        float inter = 0.f;
        #pragma unroll
        for (int cc = 0; cc < NCHUNK; cc++) inter += g_partial[b][cc];
        float flen = (float)len;
        float dice = (2.0f * inter + 1.0f) / (2.0f * flen + 1.0f);
        out[b] = 1.0f - dice;
    }
}

// ---------------------------------------------------------------------------
extern "C" void kernel_launch(void* const* d_in, const int* in_sizes, int n_in,
                              void* d_out, int out_size)
{
    const float* pots    = (const float*)d_in[0];   // [B,T,N] fp32
    const int*   y_true  = (const int*)  d_in[1];   // [B,T] int32
    const int*   lengths = (const int*)  d_in[2];   // [B] int32
    const float* trans   = (const float*)d_in[3];   // [N,N] fp32
    float* out = (float*)d_out;                     // [B] fp32

    plan_kernel<<<1, 1024>>>(lengths);
    fb_kernel<<<NWORK_MAX / WPB, 32 * WPB>>>(pots, lengths, trans);
    combine_kernel<<<dim3(BB, NCHUNK), 256>>>(y_true, lengths, out);
}

// round 15
// speedup vs baseline: 1.0674x; 1.0674x over previous
#include <cuda_runtime.h>
#include <cuda_bf16.h>
#include <cstdint>

#define BB 128
#define TT 4096
#define NN 32
#define FULL 0xffffffffu
#define KSEG 32                 // segments per chain
#define SEGLEN (TT / KSEG)      // 128
#define WARM 8                  // warm-up steps (Hilbert contraction burn-in)
#define WPB 8                   // warps per block in fb
#define NWORK_MAX (2 * BB * KSEG)
#define NCHUNK 16
#define CHUNK (TT / NCHUNK)

// bf16 tapes for scaled forward/backward messages (scale cancels in ratios).
__device__ __nv_bfloat16 g_a[(size_t)BB * TT * NN];
__device__ __nv_bfloat16 g_b[(size_t)BB * TT * NN];
__device__ float g_partial[BB][NCHUNK];
__device__ int   g_arrive[BB];   // zero-init; self-resetting (last block clears)

__device__ __forceinline__ __nv_bfloat162 asbf2(unsigned int u) {
    __nv_bfloat162 h;
    *reinterpret_cast<unsigned int*>(&h) = u;
    return h;
}

// Matvec step, bf16 state end-to-end: broadcast v via STS.16 into a 64B smem
// row, read back as 4x LDS.128 (16 bf16x2 operands), 16 HFMA2 against the
// bf16x2-packed E, 3 HADD2 + 1 HADD tree. Returns the raw dot s (bf16); the
// renorm factor rcp(v0) is returned separately (fp32, computed off-path).
__device__ __forceinline__ __nv_bfloat16 matvec_bf16(__nv_bfloat16 v,
                                                     unsigned int srow,
                                                     int lane,
                                                     const __nv_bfloat162* E2,
                                                     float& rout)
{
    unsigned short vs;
    *reinterpret_cast<__nv_bfloat16*>(&vs) = v;
    asm volatile("st.shared.u16 [%0], %1;"
                 :: "r"(srow + 2u * (unsigned)lane), "h"(vs) : "memory");
    __syncwarp();
    unsigned int w0, w1, w2, w3, w4, w5, w6, w7, w8, w9, wa, wb, wc, wd, we, wf;
    asm volatile("ld.shared.v4.u32 {%0,%1,%2,%3}, [%4];"
                 : "=r"(w0), "=r"(w1), "=r"(w2), "=r"(w3) : "r"(srow));
    asm volatile("ld.shared.v4.u32 {%0,%1,%2,%3}, [%4];"
                 : "=r"(w4), "=r"(w5), "=r"(w6), "=r"(w7) : "r"(srow + 16u));
    asm volatile("ld.shared.v4.u32 {%0,%1,%2,%3}, [%4];"
                 : "=r"(w8), "=r"(w9), "=r"(wa), "=r"(wb) : "r"(srow + 32u));
    asm volatile("ld.shared.v4.u32 {%0,%1,%2,%3}, [%4];"
                 : "=r"(wc), "=r"(wd), "=r"(we), "=r"(wf) : "r"(srow + 48u));

    rout = __frcp_rn(__low2float(asbf2(w0)));     // renorm, off critical path

    __nv_bfloat162 z = __floats2bfloat162_rn(0.f, 0.f);
    __nv_bfloat162 acc0 = z, acc1 = z, acc2 = z, acc3 = z;
    acc0 = __hfma2(asbf2(w0), E2[0],  acc0);
    acc1 = __hfma2(asbf2(w1), E2[1],  acc1);
    acc2 = __hfma2(asbf2(w2), E2[2],  acc2);
    acc3 = __hfma2(asbf2(w3), E2[3],  acc3);
    acc0 = __hfma2(asbf2(w4), E2[4],  acc0);
    acc1 = __hfma2(asbf2(w5), E2[5],  acc1);
    acc2 = __hfma2(asbf2(w6), E2[6],  acc2);
    acc3 = __hfma2(asbf2(w7), E2[7],  acc3);
    acc0 = __hfma2(asbf2(w8), E2[8],  acc0);
    acc1 = __hfma2(asbf2(w9), E2[9],  acc1);
    acc2 = __hfma2(asbf2(wa), E2[10], acc2);
    acc3 = __hfma2(asbf2(wb), E2[11], acc3);
    acc0 = __hfma2(asbf2(wc), E2[12], acc0);
    acc1 = __hfma2(asbf2(wd), E2[13], acc1);
    acc2 = __hfma2(asbf2(we), E2[14], acc2);
    acc3 = __hfma2(asbf2(wf), E2[15], acc3);

    __nv_bfloat162 tsum = __hadd2(__hadd2(acc0, acc1), __hadd2(acc2, acc3));
    return __hadd(__low2bfloat16(tsum), __high2bfloat16(tsum));
}

// ---------------------------------------------------------------------------
// Kernel 1: segmented forward/backward recursions. The work list is decoded
// INLINE per warp (~40 instr): lane l int4-loads lengths[4l..4l+3], computes
// per-batch item counts 2*nseg, warp-prefix-scans them, ballots for the
// owning lane of item gw, broadcasts and decodes (b, dir, seg). Ordering is
// identical to the old g_work list; no plan kernel, no global state.
// One warp per live item, lane = state. Probability-domain recursion with
// per-step rescale (scale cancels in marginal ratios -> no log/lse).
// Mid-chain segments start WARM steps early from a uniform positive vector;
// diag(P)E^T contracts direction error ~0.32x/step (Hilbert metric)
// => ~1e-4 after 8 steps (averages out in the dice sums). Boundary segments
// use the exact init. State carried in bf16; bf16(r*P) applied off-path.
// ---------------------------------------------------------------------------
__global__ void __launch_bounds__(32 * WPB)
fb_kernel(const float* __restrict__ pots,
          const int*   __restrict__ lengths,
          const float* __restrict__ trans)
{
    __shared__ __align__(16) __nv_bfloat16 buf[WPB][NN];

    const int lane = threadIdx.x & 31;
    const int w    = threadIdx.x >> 5;
    const int gw   = blockIdx.x * WPB + w;

    // ---- inline plan: decode gw -> (b, fwd, seg) over live items ----------
    int4 L = *reinterpret_cast<const int4*>(lengths + 4 * lane);
    int c0 = 2 * ((L.x + SEGLEN - 1) / SEGLEN);
    int c1 = 2 * ((L.y + SEGLEN - 1) / SEGLEN);
    int c2 = 2 * ((L.z + SEGLEN - 1) / SEGLEN);
    int c3 = 2 * ((L.w + SEGLEN - 1) / SEGLEN);
    int lane_sum = (c0 + c1) + (c2 + c3);
    int scan = lane_sum;
    #pragma unroll
    for (int off = 1; off < 32; off <<= 1) {
        int n = __shfl_up_sync(FULL, scan, off);
        if (lane >= off) scan += n;
    }
    const int total = __shfl_sync(FULL, scan, 31);
    if (gw >= total) return;
    const int lane_off = scan - lane_sum;      // exclusive prefix
    unsigned int mask = __ballot_sync(FULL, lane_off <= gw);
    const int owner = 31 - __clz(mask);
    int oc0 = __shfl_sync(FULL, c0, owner);
    int oc1 = __shfl_sync(FULL, c1, owner);
    int oc2 = __shfl_sync(FULL, c2, owner);
    int ooff = __shfl_sync(FULL, lane_off, owner);
    int rem = gw - ooff;
    int b = 4 * owner;
    if (rem >= oc0) { rem -= oc0; b++;
        if (rem >= oc1) { rem -= oc1; b++;
            if (rem >= oc2) { rem -= oc2; b++; } } }
    const int seg  = rem >> 1;
    const bool fwd = (rem & 1) == 0;
    // -----------------------------------------------------------------------

    const int len = lengths[b];
    const int t0  = seg * SEGLEN;                // t0 < len by construction
    int t1 = t0 + SEGLEN; if (t1 > len) t1 = len;

    const float* pot = pots + (size_t)b * TT * NN;
    const unsigned int srow =
        (unsigned int)__cvta_generic_to_shared(&buf[w][0]);

    __nv_bfloat162 E2[16];                       // packed exp(trans) pairs

    if (fwd) {
        // pair k packs exp(trans[2k][lane]), exp(trans[2k+1][lane])
        #pragma unroll
        for (int k = 0; k < 16; k++)
            E2[k] = __floats2bfloat162_rn(__expf(trans[(2 * k)     * NN + lane]),
                                          __expf(trans[(2 * k + 1) * NN + lane]));

        __nv_bfloat16* A = g_a + (size_t)b * TT * NN;

        int tstart = t0 - WARM; if (tstart < 0) tstart = 0;
        __nv_bfloat16 a;
        if (tstart == 0) {
            a = __float2bfloat16(__expf(pot[lane]));
            if (t0 == 0) A[lane] = a;
        } else {
            a = __float2bfloat16(1.0f);
        }

        const int tmain = (t0 > tstart + 1) ? t0 : tstart + 1;  // first stored t
        const float* pp = pot + (size_t)(tstart + 1) * NN + lane;
        float pr = *pp;
        float r;

        // warm-up: t in [tstart+1, t0), no stores
        for (int t = tstart + 1; t < t0; ++t) {
            float P = __expf(pr);
            pp += NN; pr = *pp;
            __nv_bfloat16 s = matvec_bf16(a, srow, lane, E2, r);
            a = __hmul(s, __float2bfloat16(r * P));
        }
        // main: t in [tmain, t1-1) with prefetch (stays <= t1-1 <= TT-1)
        __nv_bfloat16* Ap = A + (size_t)tmain * NN + lane;
        for (int t = tmain; t < t1 - 1; ++t) {
            float P = __expf(pr);
            pp += NN; pr = *pp;
            __nv_bfloat16 s = matvec_bf16(a, srow, lane, E2, r);
            a = __hmul(s, __float2bfloat16(r * P));
            *Ap = a; Ap += NN;
        }
        // peeled final step t = t1-1 (no prefetch)
        if (t1 - 1 >= tmain) {
            float P = __expf(pr);
            __nv_bfloat16 s = matvec_bf16(a, srow, lane, E2, r);
            a = __hmul(s, __float2bfloat16(r * P));
            *Ap = a;
        }
    } else {
        // pair k packs exp(trans[lane][2k]), exp(trans[lane][2k+1])
        #pragma unroll
        for (int k = 0; k < 16; k++)
            E2[k] = __floats2bfloat162_rn(__expf(trans[lane * NN + 2 * k]),
                                          __expf(trans[lane * NN + 2 * k + 1]));

        __nv_bfloat16* Bv = g_b + (size_t)b * TT * NN;

        int tstart = t1 - 1 + WARM; if (tstart > len - 1) tstart = len - 1;
        __nv_bfloat16 bv = __float2bfloat16(1.0f);   // exact at len-1
        if (tstart < t1) Bv[(size_t)tstart * NN + lane] = bv;

        const float* pp = pot + (size_t)tstart * NN + lane;
        float pr = *pp;
        float r;
        int t = tstart;

        // warm-up: t in (t1, tstart], produce unstored b_{t-1}
        for (; t > t1; --t) {
            __nv_bfloat16 Pb = __float2bfloat16(__expf(pr));
            pp -= NN; pr = *pp;
            __nv_bfloat16 s = matvec_bf16(__hmul(bv, Pb), srow, lane, E2, r);
            bv = __hmul(s, __float2bfloat16(r));
        }
        // main: t down to t0+2 with prefetch (prefetch reads >= t0+1 >= 1)
        __nv_bfloat16* Bp = Bv + (size_t)(t - 1) * NN + lane;
        for (; t >= t0 + 2; --t) {
            __nv_bfloat16 Pb = __float2bfloat16(__expf(pr));
            pp -= NN; pr = *pp;
            __nv_bfloat16 s = matvec_bf16(__hmul(bv, Pb), srow, lane, E2, r);
            bv = __hmul(s, __float2bfloat16(r));
            *Bp = bv; Bp -= NN;
        }
        // peeled final step t = t0+1 (no prefetch; avoids reading row t0-1)
        if (t == t0 + 1) {
            __nv_bfloat16 Pb = __float2bfloat16(__expf(pr));
            __nv_bfloat16 s = matvec_bf16(__hmul(bv, Pb), srow, lane, E2, r);
            bv = __hmul(s, __float2bfloat16(r));
            *Bp = bv;
        }
    }
}

// ---------------------------------------------------------------------------
// Kernel 2: combine partials over bf16 tapes + fused finalize. grid
// (BB, NCHUNK); block (b,c) handles t in [c*CHUNK, (c+1)*CHUNK) ∩ [0,len),
// writes its partial slot, then the LAST block to arrive for batch b
// (atomic counter; fixed summation order -> deterministic) sums the NCHUNK
// partials, writes out[b], and resets the counter (self-cleaning across
// graph replays; zero-init covers the first call).
// p_t(y_t) = a_y b_y / sum_k a_k b_k (per-t scales cancel).
// ---------------------------------------------------------------------------
__device__ __forceinline__ float2 bf2f(unsigned int u) {
    return __bfloat1622float2(asbf2(u));
}

__global__ void __launch_bounds__(256)
combine_kernel(const int* __restrict__ y_true,
               const int* __restrict__ lengths,
               float*     __restrict__ out)
{
    const int b   = blockIdx.x;
    const int c   = blockIdx.y;
    const int tid = threadIdx.x;
    const int len = lengths[b];

    const int t_lo = c * CHUNK;
    int t_hi = t_lo + CHUNK; if (t_hi > len) t_hi = len;

    const __nv_bfloat16* Ab = g_a + (size_t)b * TT * NN;
    const __nv_bfloat16* Bb = g_b + (size_t)b * TT * NN;
    const int* Yb = y_true + (size_t)b * TT;

    float part = 0.f;
    for (int t = t_lo + tid; t < t_hi; t += 256) {
        const uint4* A4 = reinterpret_cast<const uint4*>(Ab + (size_t)t * NN);
        const uint4* B4 = reinterpret_cast<const uint4*>(Bb + (size_t)t * NN);
        int y = Yb[t];
        float s = 0.f, py = 0.f;
        #pragma unroll
        for (int q = 0; q < 4; q++) {
            uint4 ua = __ldcs(&A4[q]);
            uint4 ub = __ldcs(&B4[q]);
            unsigned int aw[4] = {ua.x, ua.y, ua.z, ua.w};
            unsigned int bw[4] = {ub.x, ub.y, ub.z, ub.w};
            #pragma unroll
            for (int i = 0; i < 4; i++) {
                float2 fa = bf2f(aw[i]);
                float2 fb = bf2f(bw[i]);
                s = fmaf(fa.x, fb.x, s);
                s = fmaf(fa.y, fb.y, s);
                if ((y >> 1) == q * 4 + i)
                    py = (y & 1) ? fa.y * fb.y : fa.x * fb.x;
            }
        }
        part += __fdividef(py, s);
    }

    #pragma unroll
    for (int off = 16; off > 0; off >>= 1)
        part += __shfl_down_sync(FULL, part, off);

    __shared__ float red[8];
    __shared__ int last;
    if ((tid & 31) == 0) red[tid >> 5] = part;
    __syncthreads();
    if (tid == 0) {
        float s = 0.f;
        #pragma unroll
        for (int w2 = 0; w2 < 8; w2++) s += red[w2];
        g_partial[b][c] = s;
        __threadfence();
        int prev = atomicAdd(&g_arrive[b], 1);
        last = (prev == NCHUNK - 1) ? 1 : 0;
    }
    __syncthreads();
    if (last && tid == 0) {
        float inter = 0.f;
        #pragma unroll
        for (int cc = 0; cc < NCHUNK; cc++) inter += g_partial[b][cc];
        float flen = (float)len;
        float dice = (2.0f * inter + 1.0f) / (2.0f * flen + 1.0f);
        out[b] = 1.0f - dice;
        g_arrive[b] = 0;                 // self-reset for the next replay
    }
}

// ---------------------------------------------------------------------------
extern "C" void kernel_launch(void* const* d_in, const int* in_sizes, int n_in,
                              void* d_out, int out_size)
{
    const float* pots    = (const float*)d_in[0];   // [B,T,N] fp32
    const int*   y_true  = (const int*)  d_in[1];   // [B,T] int32
    const int*   lengths = (const int*)  d_in[2];   // [B] int32
    const float* trans   = (const float*)d_in[3];   // [N,N] fp32
    float* out = (float*)d_out;                     // [B] fp32

    fb_kernel<<<NWORK_MAX / WPB, 32 * WPB>>>(pots, lengths, trans);
    combine_kernel<<<dim3(BB, NCHUNK), 256>>>(y_true, lengths, out);
}

// round 16
// speedup vs baseline: 1.0736x; 1.0058x over previous
#include <cuda_runtime.h>
#include <cuda_bf16.h>
#include <cstdint>

#define BB 128
#define TT 4096
#define NN 32
#define FULL 0xffffffffu
#define KSEG 32                 // segments per chain
#define SEGLEN (TT / KSEG)      // 128
#define WARM 8                  // warm-up steps (Hilbert contraction burn-in)
#define WPB 8                   // warps per block in fb
#define NWORK_MAX (2 * BB * KSEG)
#define NCHUNK 16
#define CHUNK (TT / NCHUNK)

// bf16 tapes for scaled forward/backward messages (scale cancels in ratios).
__device__ __nv_bfloat16 g_a[(size_t)BB * TT * NN];
__device__ __nv_bfloat16 g_b[(size_t)BB * TT * NN];
__device__ float g_partial[BB][NCHUNK];
__device__ int   g_arrive[BB];   // zero-init; self-resetting (last block clears)

__device__ __forceinline__ __nv_bfloat162 asbf2(unsigned int u) {
    __nv_bfloat162 h;
    *reinterpret_cast<unsigned int*>(&h) = u;
    return h;
}

// Matvec step, bf16 state end-to-end: broadcast v via STS.16 into a 64B smem
// row, read back as 4x LDS.128 (16 bf16x2 operands), 16 HFMA2 against the
// bf16x2-packed E, 3 HADD2 + 1 HADD tree. Returns the raw dot s (bf16); the
// renorm factor rcp(v0) is returned separately (fp32, computed off-path).
__device__ __forceinline__ __nv_bfloat16 matvec_bf16(__nv_bfloat16 v,
                                                     unsigned int srow,
                                                     int lane,
                                                     const __nv_bfloat162* E2,
                                                     float& rout)
{
    unsigned short vs;
    *reinterpret_cast<__nv_bfloat16*>(&vs) = v;
    asm volatile("st.shared.u16 [%0], %1;"
                 :: "r"(srow + 2u * (unsigned)lane), "h"(vs) : "memory");
    __syncwarp();
    unsigned int w0, w1, w2, w3, w4, w5, w6, w7, w8, w9, wa, wb, wc, wd, we, wf;
    asm volatile("ld.shared.v4.u32 {%0,%1,%2,%3}, [%4];"
                 : "=r"(w0), "=r"(w1), "=r"(w2), "=r"(w3) : "r"(srow));
    asm volatile("ld.shared.v4.u32 {%0,%1,%2,%3}, [%4];"
                 : "=r"(w4), "=r"(w5), "=r"(w6), "=r"(w7) : "r"(srow + 16u));
    asm volatile("ld.shared.v4.u32 {%0,%1,%2,%3}, [%4];"
                 : "=r"(w8), "=r"(w9), "=r"(wa), "=r"(wb) : "r"(srow + 32u));
    asm volatile("ld.shared.v4.u32 {%0,%1,%2,%3}, [%4];"
                 : "=r"(wc), "=r"(wd), "=r"(we), "=r"(wf) : "r"(srow + 48u));

    rout = __frcp_rn(__low2float(asbf2(w0)));     // renorm, off critical path

    __nv_bfloat162 z = __floats2bfloat162_rn(0.f, 0.f);
    __nv_bfloat162 acc0 = z, acc1 = z, acc2 = z, acc3 = z;
    acc0 = __hfma2(asbf2(w0), E2[0],  acc0);
    acc1 = __hfma2(asbf2(w1), E2[1],  acc1);
    acc2 = __hfma2(asbf2(w2), E2[2],  acc2);
    acc3 = __hfma2(asbf2(w3), E2[3],  acc3);
    acc0 = __hfma2(asbf2(w4), E2[4],  acc0);
    acc1 = __hfma2(asbf2(w5), E2[5],  acc1);
    acc2 = __hfma2(asbf2(w6), E2[6],  acc2);
    acc3 = __hfma2(asbf2(w7), E2[7],  acc3);
    acc0 = __hfma2(asbf2(w8), E2[8],  acc0);
    acc1 = __hfma2(asbf2(w9), E2[9],  acc1);
    acc2 = __hfma2(asbf2(wa), E2[10], acc2);
    acc3 = __hfma2(asbf2(wb), E2[11], acc3);
    acc0 = __hfma2(asbf2(wc), E2[12], acc0);
    acc1 = __hfma2(asbf2(wd), E2[13], acc1);
    acc2 = __hfma2(asbf2(we), E2[14], acc2);
    acc3 = __hfma2(asbf2(wf), E2[15], acc3);

    __nv_bfloat162 tsum = __hadd2(__hadd2(acc0, acc1), __hadd2(acc2, acc3));
    return __hadd(__low2bfloat16(tsum), __high2bfloat16(tsum));
}

// ---------------------------------------------------------------------------
// Kernel 1: segmented forward/backward recursions. The work list is decoded
// INLINE per warp (~40 instr): lane l int4-loads lengths[4l..4l+3], computes
// per-batch item counts 2*nseg, warp-prefix-scans them, ballots for the
// owning lane of item gw, broadcasts and decodes (b, dir, seg).
// One warp per live item, lane = state. Probability-domain recursion with
// per-step rescale (scale cancels in marginal ratios -> no log/lse).
// Mid-chain segments start WARM steps early from a uniform positive vector;
// diag(P)E^T contracts direction error ~0.32x/step (Hilbert metric)
// => ~1e-4 after 8 steps (averages out in the dice sums). Boundary segments
// use the exact init. State carried in bf16; bf16(r*P) applied off-path.
// ---------------------------------------------------------------------------
__global__ void __launch_bounds__(32 * WPB)
fb_kernel(const float* __restrict__ pots,
          const int*   __restrict__ lengths,
          const float* __restrict__ trans)
{
    __shared__ __align__(16) __nv_bfloat16 buf[WPB][NN];

    const int lane = threadIdx.x & 31;
    const int w    = threadIdx.x >> 5;
    const int gw   = blockIdx.x * WPB + w;

    // ---- inline plan: decode gw -> (b, fwd, seg) over live items ----------
    int4 L = *reinterpret_cast<const int4*>(lengths + 4 * lane);
    int c0 = 2 * ((L.x + SEGLEN - 1) / SEGLEN);
    int c1 = 2 * ((L.y + SEGLEN - 1) / SEGLEN);
    int c2 = 2 * ((L.z + SEGLEN - 1) / SEGLEN);
    int c3 = 2 * ((L.w + SEGLEN - 1) / SEGLEN);
    int lane_sum = (c0 + c1) + (c2 + c3);
    int scan = lane_sum;
    #pragma unroll
    for (int off = 1; off < 32; off <<= 1) {
        int n = __shfl_up_sync(FULL, scan, off);
        if (lane >= off) scan += n;
    }
    const int total = __shfl_sync(FULL, scan, 31);
    if (gw >= total) return;
    const int lane_off = scan - lane_sum;      // exclusive prefix
    unsigned int mask = __ballot_sync(FULL, lane_off <= gw);
    const int owner = 31 - __clz(mask);
    int oc0 = __shfl_sync(FULL, c0, owner);
    int oc1 = __shfl_sync(FULL, c1, owner);
    int oc2 = __shfl_sync(FULL, c2, owner);
    int ooff = __shfl_sync(FULL, lane_off, owner);
    int rem = gw - ooff;
    int b = 4 * owner;
    if (rem >= oc0) { rem -= oc0; b++;
        if (rem >= oc1) { rem -= oc1; b++;
            if (rem >= oc2) { rem -= oc2; b++; } } }
    const int seg  = rem >> 1;
    const bool fwd = (rem & 1) == 0;
    // -----------------------------------------------------------------------

    const int len = lengths[b];
    const int t0  = seg * SEGLEN;                // t0 < len by construction
    int t1 = t0 + SEGLEN; if (t1 > len) t1 = len;

    const float* pot = pots + (size_t)b * TT * NN;
    const unsigned int srow =
        (unsigned int)__cvta_generic_to_shared(&buf[w][0]);

    __nv_bfloat162 E2[16];                       // packed exp(trans) pairs

    if (fwd) {
        // pair k packs exp(trans[2k][lane]), exp(trans[2k+1][lane])
        #pragma unroll
        for (int k = 0; k < 16; k++)
            E2[k] = __floats2bfloat162_rn(__expf(trans[(2 * k)     * NN + lane]),
                                          __expf(trans[(2 * k + 1) * NN + lane]));

        __nv_bfloat16* A = g_a + (size_t)b * TT * NN;

        int tstart = t0 - WARM; if (tstart < 0) tstart = 0;
        __nv_bfloat16 a;
        if (tstart == 0) {
            a = __float2bfloat16(__expf(pot[lane]));
            if (t0 == 0) A[lane] = a;
        } else {
            a = __float2bfloat16(1.0f);
        }

        const int tmain = (t0 > tstart + 1) ? t0 : tstart + 1;  // first stored t
        const float* pp = pot + (size_t)(tstart + 1) * NN + lane;
        float pr = *pp;
        float r;

        // warm-up: t in [tstart+1, t0), no stores
        for (int t = tstart + 1; t < t0; ++t) {
            float P = __expf(pr);
            pp += NN; pr = *pp;
            __nv_bfloat16 s = matvec_bf16(a, srow, lane, E2, r);
            a = __hmul(s, __float2bfloat16(r * P));
        }
        // main: t in [tmain, t1-1) with prefetch (stays <= t1-1 <= TT-1)
        __nv_bfloat16* Ap = A + (size_t)tmain * NN + lane;
        for (int t = tmain; t < t1 - 1; ++t) {
            float P = __expf(pr);
            pp += NN; pr = *pp;
            __nv_bfloat16 s = matvec_bf16(a, srow, lane, E2, r);
            a = __hmul(s, __float2bfloat16(r * P));
            *Ap = a; Ap += NN;
        }
        // peeled final step t = t1-1 (no prefetch)
        if (t1 - 1 >= tmain) {
            float P = __expf(pr);
            __nv_bfloat16 s = matvec_bf16(a, srow, lane, E2, r);
            a = __hmul(s, __float2bfloat16(r * P));
            *Ap = a;
        }
    } else {
        // pair k packs exp(trans[lane][2k]), exp(trans[lane][2k+1])
        #pragma unroll
        for (int k = 0; k < 16; k++)
            E2[k] = __floats2bfloat162_rn(__expf(trans[lane * NN + 2 * k]),
                                          __expf(trans[lane * NN + 2 * k + 1]));

        __nv_bfloat16* Bv = g_b + (size_t)b * TT * NN;

        int tstart = t1 - 1 + WARM; if (tstart > len - 1) tstart = len - 1;
        __nv_bfloat16 bv = __float2bfloat16(1.0f);   // exact at len-1
        if (tstart < t1) Bv[(size_t)tstart * NN + lane] = bv;

        const float* pp = pot + (size_t)tstart * NN + lane;
        float pr = *pp;
        float r;
        int t = tstart;

        // warm-up: t in (t1, tstart], produce unstored b_{t-1}
        for (; t > t1; --t) {
            __nv_bfloat16 Pb = __float2bfloat16(__expf(pr));
            pp -= NN; pr = *pp;
            __nv_bfloat16 s = matvec_bf16(__hmul(bv, Pb), srow, lane, E2, r);
            bv = __hmul(s, __float2bfloat16(r));
        }
        // main: t down to t0+2 with prefetch (prefetch reads >= t0+1 >= 1)
        __nv_bfloat16* Bp = Bv + (size_t)(t - 1) * NN + lane;
        for (; t >= t0 + 2; --t) {
            __nv_bfloat16 Pb = __float2bfloat16(__expf(pr));
            pp -= NN; pr = *pp;
            __nv_bfloat16 s = matvec_bf16(__hmul(bv, Pb), srow, lane, E2, r);
            bv = __hmul(s, __float2bfloat16(r));
            *Bp = bv; Bp -= NN;
        }
        // peeled final step t = t0+1 (no prefetch; avoids reading row t0-1)
        if (t == t0 + 1) {
            __nv_bfloat16 Pb = __float2bfloat16(__expf(pr));
            __nv_bfloat16 s = matvec_bf16(__hmul(bv, Pb), srow, lane, E2, r);
            bv = __hmul(s, __float2bfloat16(r));
            *Bp = bv;
        }
    }
}

// ---------------------------------------------------------------------------
// Kernel 2: combine partials over bf16 tapes + fused finalize. grid
// (BB, NCHUNK). The y-element is fetched with two scalar bf16 loads (L1/L2
// hits right after the row loads) instead of in-register selection: the
// 32-FMA dot runs with zero compare/select ALU. Last block per batch
// (atomic counter, fixed order -> deterministic) writes out[b] and resets
// the counter. p_t(y_t) = a_y b_y / sum_k a_k b_k (per-t scales cancel).
// ---------------------------------------------------------------------------
__device__ __forceinline__ float2 bf2f(unsigned int u) {
    return __bfloat1622float2(asbf2(u));
}

__global__ void __launch_bounds__(256)
combine_kernel(const int* __restrict__ y_true,
               const int* __restrict__ lengths,
               float*     __restrict__ out)
{
    const int b   = blockIdx.x;
    const int c   = blockIdx.y;
    const int tid = threadIdx.x;
    const int len = lengths[b];

    const int t_lo = c * CHUNK;
    int t_hi = t_lo + CHUNK; if (t_hi > len) t_hi = len;

    const __nv_bfloat16* Ab = g_a + (size_t)b * TT * NN;
    const __nv_bfloat16* Bb = g_b + (size_t)b * TT * NN;
    const int* Yb = y_true + (size_t)b * TT;

    float part = 0.f;
    for (int t = t_lo + tid; t < t_hi; t += 256) {
        const uint4* A4 = reinterpret_cast<const uint4*>(Ab + (size_t)t * NN);
        const uint4* B4 = reinterpret_cast<const uint4*>(Bb + (size_t)t * NN);
        const int y = Yb[t];
        uint4 ua0 = __ldcs(&A4[0]);
        uint4 ua1 = __ldcs(&A4[1]);
        uint4 ua2 = __ldcs(&A4[2]);
        uint4 ua3 = __ldcs(&A4[3]);
        uint4 ub0 = __ldcs(&B4[0]);
        uint4 ub1 = __ldcs(&B4[1]);
        uint4 ub2 = __ldcs(&B4[2]);
        uint4 ub3 = __ldcs(&B4[3]);
        // scalar y-element loads: same lines, L1/L2 hits, off the dot path
        float ay = __bfloat162float(Ab[(size_t)t * NN + y]);
        float by = __bfloat162float(Bb[(size_t)t * NN + y]);

        float s = 0.f;
        unsigned int aw[16] = {ua0.x, ua0.y, ua0.z, ua0.w,
                               ua1.x, ua1.y, ua1.z, ua1.w,
                               ua2.x, ua2.y, ua2.z, ua2.w,
                               ua3.x, ua3.y, ua3.z, ua3.w};
        unsigned int bw[16] = {ub0.x, ub0.y, ub0.z, ub0.w,
                               ub1.x, ub1.y, ub1.z, ub1.w,
                               ub2.x, ub2.y, ub2.z, ub2.w,
                               ub3.x, ub3.y, ub3.z, ub3.w};
        #pragma unroll
        for (int i = 0; i < 16; i++) {
            float2 fa = bf2f(aw[i]);
            float2 fb = bf2f(bw[i]);
            s = fmaf(fa.x, fb.x, s);
            s = fmaf(fa.y, fb.y, s);
        }
        part += __fdividef(ay * by, s);
    }

    #pragma unroll
    for (int off = 16; off > 0; off >>= 1)
        part += __shfl_down_sync(FULL, part, off);

    __shared__ float red[8];
    __shared__ int last;
    if ((tid & 31) == 0) red[tid >> 5] = part;
    __syncthreads();
    if (tid == 0) {
        float s = 0.f;
        #pragma unroll
        for (int w2 = 0; w2 < 8; w2++) s += red[w2];
        g_partial[b][c] = s;
        __threadfence();
        int prev = atomicAdd(&g_arrive[b], 1);
        last = (prev == NCHUNK - 1) ? 1 : 0;
    }
    __syncthreads();
    if (last && tid == 0) {
        float inter = 0.f;
        #pragma unroll
        for (int cc = 0; cc < NCHUNK; cc++) inter += g_partial[b][cc];
        float flen = (float)len;
        float dice = (2.0f * inter + 1.0f) / (2.0f * flen + 1.0f);
        out[b] = 1.0f - dice;
        g_arrive[b] = 0;                 // self-reset for the next replay
    }
}

// ---------------------------------------------------------------------------
extern "C" void kernel_launch(void* const* d_in, const int* in_sizes, int n_in,
                              void* d_out, int out_size)
{
    const float* pots    = (const float*)d_in[0];   // [B,T,N] fp32
    const int*   y_true  = (const int*)  d_in[1];   // [B,T] int32
    const int*   lengths = (const int*)  d_in[2];   // [B] int32
    const float* trans   = (const float*)d_in[3];   // [N,N] fp32
    float* out = (float*)d_out;                     // [B] fp32

    fb_kernel<<<NWORK_MAX / WPB, 32 * WPB>>>(pots, lengths, trans);
    combine_kernel<<<dim3(BB, NCHUNK), 256>>>(y_true, lengths, out);
}

// round 17
// speedup vs baseline: 1.0833x; 1.0091x over previous
#include <cuda_runtime.h>
#include <cuda_bf16.h>
#include <cstdint>

#define BB 128
#define TT 4096
#define NN 32
#define FULL 0xffffffffu
#define KSEG 32                 // segments per chain
#define SEGLEN (TT / KSEG)      // 128
#define WARM 8                  // warm-up steps (Hilbert contraction burn-in)
#define WPB 8                   // warps per block in fb
#define NWORK_MAX (2 * BB * KSEG)
#define NCHUNK 16
#define CHUNK (TT / NCHUNK)

// bf16 tapes for scaled forward/backward messages (scale cancels in ratios).
__device__ __nv_bfloat16 g_a[(size_t)BB * TT * NN];
__device__ __nv_bfloat16 g_b[(size_t)BB * TT * NN];
__device__ float g_partial[BB][NCHUNK];
__device__ int   g_arrive[BB];   // zero-init; self-resetting (last block clears)

__device__ __forceinline__ __nv_bfloat162 asbf2(unsigned int u) {
    __nv_bfloat162 h;
    *reinterpret_cast<unsigned int*>(&h) = u;
    return h;
}

// Matvec step, bf16 state end-to-end: broadcast v via STS.16 into a 64B smem
// row, read back as 4x LDS.128 (16 bf16x2 operands), 16 HFMA2 against the
// bf16x2-packed E, 3 HADD2 + 1 HADD tree. NO warp barrier: the calling warp
// is convergent through the hot loop (all branches warp-uniform), and a
// converged warp issues its STS strictly before its LDS (in-order per-warp
// LSU), so the store is visible to all lanes' loads. asm volatile + memory
// clobbers pin compiler ordering. Returns raw dot s (bf16); renorm factor
// rcp(v0) returned separately (fp32, computed off the critical path).
__device__ __forceinline__ __nv_bfloat16 matvec_bf16(__nv_bfloat16 v,
                                                     unsigned int srow,
                                                     int lane,
                                                     const __nv_bfloat162* E2,
                                                     float& rout)
{
    unsigned short vs;
    *reinterpret_cast<__nv_bfloat16*>(&vs) = v;
    asm volatile("st.shared.u16 [%0], %1;"
                 :: "r"(srow + 2u * (unsigned)lane), "h"(vs) : "memory");
    unsigned int w0, w1, w2, w3, w4, w5, w6, w7, w8, w9, wa, wb, wc, wd, we, wf;
    asm volatile("ld.shared.v4.u32 {%0,%1,%2,%3}, [%4];"
                 : "=r"(w0), "=r"(w1), "=r"(w2), "=r"(w3) : "r"(srow) : "memory");
    asm volatile("ld.shared.v4.u32 {%0,%1,%2,%3}, [%4];"
                 : "=r"(w4), "=r"(w5), "=r"(w6), "=r"(w7) : "r"(srow + 16u) : "memory");
    asm volatile("ld.shared.v4.u32 {%0,%1,%2,%3}, [%4];"
                 : "=r"(w8), "=r"(w9), "=r"(wa), "=r"(wb) : "r"(srow + 32u) : "memory");
    asm volatile("ld.shared.v4.u32 {%0,%1,%2,%3}, [%4];"
                 : "=r"(wc), "=r"(wd), "=r"(we), "=r"(wf) : "r"(srow + 48u) : "memory");

    rout = __frcp_rn(__low2float(asbf2(w0)));     // renorm, off critical path

    __nv_bfloat162 z = __floats2bfloat162_rn(0.f, 0.f);
    __nv_bfloat162 acc0 = z, acc1 = z, acc2 = z, acc3 = z;
    acc0 = __hfma2(asbf2(w0), E2[0],  acc0);
    acc1 = __hfma2(asbf2(w1), E2[1],  acc1);
    acc2 = __hfma2(asbf2(w2), E2[2],  acc2);
    acc3 = __hfma2(asbf2(w3), E2[3],  acc3);
    acc0 = __hfma2(asbf2(w4), E2[4],  acc0);
    acc1 = __hfma2(asbf2(w5), E2[5],  acc1);
    acc2 = __hfma2(asbf2(w6), E2[6],  acc2);
    acc3 = __hfma2(asbf2(w7), E2[7],  acc3);
    acc0 = __hfma2(asbf2(w8), E2[8],  acc0);
    acc1 = __hfma2(asbf2(w9), E2[9],  acc1);
    acc2 = __hfma2(asbf2(wa), E2[10], acc2);
    acc3 = __hfma2(asbf2(wb), E2[11], acc3);
    acc0 = __hfma2(asbf2(wc), E2[12], acc0);
    acc1 = __hfma2(asbf2(wd), E2[13], acc1);
    acc2 = __hfma2(asbf2(we), E2[14], acc2);
    acc3 = __hfma2(asbf2(wf), E2[15], acc3);

    __nv_bfloat162 tsum = __hadd2(__hadd2(acc0, acc1), __hadd2(acc2, acc3));
    return __hadd(__low2bfloat16(tsum), __high2bfloat16(tsum));
}

// ---------------------------------------------------------------------------
// Kernel 1: segmented forward/backward recursions. Work list decoded INLINE
// per warp (~40 instr): lane l int4-loads lengths[4l..4l+3], computes
// per-batch item counts 2*nseg, warp-prefix-scans, ballots for the owning
// lane of item gw, broadcasts and decodes (b, dir, seg).
// One warp per live item, lane = state. Probability-domain recursion with
// per-step rescale (scale cancels in marginal ratios -> no log/lse).
// Mid-chain segments start WARM steps early from a uniform positive vector;
// diag(P)E^T contracts direction error ~0.32x/step (Hilbert metric)
// => ~1e-4 after 8 steps (averages out in the dice sums). Boundary segments
// use the exact init. State carried in bf16; bf16(r*P) applied off-path.
// ---------------------------------------------------------------------------
__global__ void __launch_bounds__(32 * WPB)
fb_kernel(const float* __restrict__ pots,
          const int*   __restrict__ lengths,
          const float* __restrict__ trans)
{
    __shared__ __align__(16) __nv_bfloat16 buf[WPB][NN];

    const int lane = threadIdx.x & 31;
    const int w    = threadIdx.x >> 5;
    const int gw   = blockIdx.x * WPB + w;

    // ---- inline plan: decode gw -> (b, fwd, seg) over live items ----------
    int4 L = *reinterpret_cast<const int4*>(lengths + 4 * lane);
    int c0 = 2 * ((L.x + SEGLEN - 1) / SEGLEN);
    int c1 = 2 * ((L.y + SEGLEN - 1) / SEGLEN);
    int c2 = 2 * ((L.z + SEGLEN - 1) / SEGLEN);
    int c3 = 2 * ((L.w + SEGLEN - 1) / SEGLEN);
    int lane_sum = (c0 + c1) + (c2 + c3);
    int scan = lane_sum;
    #pragma unroll
    for (int off = 1; off < 32; off <<= 1) {
        int n = __shfl_up_sync(FULL, scan, off);
        if (lane >= off) scan += n;
    }
    const int total = __shfl_sync(FULL, scan, 31);
    if (gw >= total) return;
    const int lane_off = scan - lane_sum;      // exclusive prefix
    unsigned int mask = __ballot_sync(FULL, lane_off <= gw);
    const int owner = 31 - __clz(mask);
    int oc0 = __shfl_sync(FULL, c0, owner);
    int oc1 = __shfl_sync(FULL, c1, owner);
    int oc2 = __shfl_sync(FULL, c2, owner);
    int ooff = __shfl_sync(FULL, lane_off, owner);
    int rem = gw - ooff;
    int b = 4 * owner;
    if (rem >= oc0) { rem -= oc0; b++;
        if (rem >= oc1) { rem -= oc1; b++;
            if (rem >= oc2) { rem -= oc2; b++; } } }
    const int seg  = rem >> 1;
    const bool fwd = (rem & 1) == 0;
    // -----------------------------------------------------------------------

    const int len = lengths[b];
    const int t0  = seg * SEGLEN;                // t0 < len by construction
    int t1 = t0 + SEGLEN; if (t1 > len) t1 = len;

    const float* pot = pots + (size_t)b * TT * NN;
    const unsigned int srow =
        (unsigned int)__cvta_generic_to_shared(&buf[w][0]);

    __nv_bfloat162 E2[16];                       // packed exp(trans) pairs

    if (fwd) {
        // pair k packs exp(trans[2k][lane]), exp(trans[2k+1][lane])
        #pragma unroll
        for (int k = 0; k < 16; k++)
            E2[k] = __floats2bfloat162_rn(__expf(trans[(2 * k)     * NN + lane]),
                                          __expf(trans[(2 * k + 1) * NN + lane]));

        __nv_bfloat16* A = g_a + (size_t)b * TT * NN;

        int tstart = t0 - WARM; if (tstart < 0) tstart = 0;
        __nv_bfloat16 a;
        if (tstart == 0) {
            a = __float2bfloat16(__expf(pot[lane]));
            if (t0 == 0) A[lane] = a;
        } else {
            a = __float2bfloat16(1.0f);
        }

        const int tmain = (t0 > tstart + 1) ? t0 : tstart + 1;  // first stored t
        const float* pp = pot + (size_t)(tstart + 1) * NN + lane;
        float pr = *pp;
        float r;

        // warm-up: t in [tstart+1, t0), no stores
        for (int t = tstart + 1; t < t0; ++t) {
            float P = __expf(pr);
            pp += NN; pr = *pp;
            __nv_bfloat16 s = matvec_bf16(a, srow, lane, E2, r);
            a = __hmul(s, __float2bfloat16(r * P));
        }
        // main: t in [tmain, t1-1) with prefetch (stays <= t1-1 <= TT-1)
        __nv_bfloat16* Ap = A + (size_t)tmain * NN + lane;
        for (int t = tmain; t < t1 - 1; ++t) {
            float P = __expf(pr);
            pp += NN; pr = *pp;
            __nv_bfloat16 s = matvec_bf16(a, srow, lane, E2, r);
            a = __hmul(s, __float2bfloat16(r * P));
            *Ap = a; Ap += NN;
        }
        // peeled final step t = t1-1 (no prefetch)
        if (t1 - 1 >= tmain) {
            float P = __expf(pr);
            __nv_bfloat16 s = matvec_bf16(a, srow, lane, E2, r);
            a = __hmul(s, __float2bfloat16(r * P));
            *Ap = a;
        }
    } else {
        // pair k packs exp(trans[lane][2k]), exp(trans[lane][2k+1])
        #pragma unroll
        for (int k = 0; k < 16; k++)
            E2[k] = __floats2bfloat162_rn(__expf(trans[lane * NN + 2 * k]),
                                          __expf(trans[lane * NN + 2 * k + 1]));

        __nv_bfloat16* Bv = g_b + (size_t)b * TT * NN;

        int tstart = t1 - 1 + WARM; if (tstart > len - 1) tstart = len - 1;
        __nv_bfloat16 bv = __float2bfloat16(1.0f);   // exact at len-1
        if (tstart < t1) Bv[(size_t)tstart * NN + lane] = bv;

        const float* pp = pot + (size_t)tstart * NN + lane;
        float pr = *pp;
        float r;
        int t = tstart;

        // warm-up: t in (t1, tstart], produce unstored b_{t-1}
        for (; t > t1; --t) {
            __nv_bfloat16 Pb = __float2bfloat16(__expf(pr));
            pp -= NN; pr = *pp;
            __nv_bfloat16 s = matvec_bf16(__hmul(bv, Pb), srow, lane, E2, r);
            bv = __hmul(s, __float2bfloat16(r));
        }
        // main: t down to t0+2 with prefetch (prefetch reads >= t0+1 >= 1)
        __nv_bfloat16* Bp = Bv + (size_t)(t - 1) * NN + lane;
        for (; t >= t0 + 2; --t) {
            __nv_bfloat16 Pb = __float2bfloat16(__expf(pr));
            pp -= NN; pr = *pp;
            __nv_bfloat16 s = matvec_bf16(__hmul(bv, Pb), srow, lane, E2, r);
            bv = __hmul(s, __float2bfloat16(r));
            *Bp = bv; Bp -= NN;
        }
        // peeled final step t = t0+1 (no prefetch; avoids reading row t0-1)
        if (t == t0 + 1) {
            __nv_bfloat16 Pb = __float2bfloat16(__expf(pr));
            __nv_bfloat16 s = matvec_bf16(__hmul(bv, Pb), srow, lane, E2, r);
            bv = __hmul(s, __float2bfloat16(r));
            *Bp = bv;
        }
    }
}

// ---------------------------------------------------------------------------
// Kernel 2: combine partials over bf16 tapes + fused finalize. grid
// (BB, NCHUNK). Rows loaded with DEFAULT cache policy (not streaming) so the
// scalar y-element loads hit L1 on the same lines; y loads issued first.
// Last block per batch (atomic counter, fixed order -> deterministic) writes
// out[b] and resets the counter.
// p_t(y_t) = a_y b_y / sum_k a_k b_k (per-t scales cancel).
// ---------------------------------------------------------------------------
__device__ __forceinline__ float2 bf2f(unsigned int u) {
    return __bfloat1622float2(asbf2(u));
}

__global__ void __launch_bounds__(256)
combine_kernel(const int* __restrict__ y_true,
               const int* __restrict__ lengths,
               float*     __restrict__ out)
{
    const int b   = blockIdx.x;
    const int c   = blockIdx.y;
    const int tid = threadIdx.x;
    const int len = lengths[b];

    const int t_lo = c * CHUNK;
    int t_hi = t_lo + CHUNK; if (t_hi > len) t_hi = len;

    const __nv_bfloat16* Ab = g_a + (size_t)b * TT * NN;
    const __nv_bfloat16* Bb = g_b + (size_t)b * TT * NN;
    const int* Yb = y_true + (size_t)b * TT;

    float part = 0.f;
    for (int t = t_lo + tid; t < t_hi; t += 256) {
        const uint4* A4 = reinterpret_cast<const uint4*>(Ab + (size_t)t * NN);
        const uint4* B4 = reinterpret_cast<const uint4*>(Bb + (size_t)t * NN);
        const int y = Yb[t];
        // y-element scalar loads first (same lines as the rows; L1-resident)
        float ay = __bfloat162float(Ab[(size_t)t * NN + y]);
        float by = __bfloat162float(Bb[(size_t)t * NN + y]);
        uint4 ua0 = A4[0];
        uint4 ua1 = A4[1];
        uint4 ua2 = A4[2];
        uint4 ua3 = A4[3];
        uint4 ub0 = B4[0];
        uint4 ub1 = B4[1];
        uint4 ub2 = B4[2];
        uint4 ub3 = B4[3];

        float s = 0.f;
        unsigned int aw[16] = {ua0.x, ua0.y, ua0.z, ua0.w,
                               ua1.x, ua1.y, ua1.z, ua1.w,
                               ua2.x, ua2.y, ua2.z, ua2.w,
                               ua3.x, ua3.y, ua3.z, ua3.w};
        unsigned int bw[16] = {ub0.x, ub0.y, ub0.z, ub0.w,
                               ub1.x, ub1.y, ub1.z, ub1.w,
                               ub2.x, ub2.y, ub2.z, ub2.w,
                               ub3.x, ub3.y, ub3.z, ub3.w};
        #pragma unroll
        for (int i = 0; i < 16; i++) {
            float2 fa = bf2f(aw[i]);
            float2 fb = bf2f(bw[i]);
            s = fmaf(fa.x, fb.x, s);
            s = fmaf(fa.y, fb.y, s);
        }
        part += __fdividef(ay * by, s);
    }

    #pragma unroll
    for (int off = 16; off > 0; off >>= 1)
        part += __shfl_down_sync(FULL, part, off);

    __shared__ float red[8];
    __shared__ int last;
    if ((tid & 31) == 0) red[tid >> 5] = part;
    __syncthreads();
    if (tid == 0) {
        float s = 0.f;
        #pragma unroll
        for (int w2 = 0; w2 < 8; w2++) s += red[w2];
        g_partial[b][c] = s;
        __threadfence();
        int prev = atomicAdd(&g_arrive[b], 1);
        last = (prev == NCHUNK - 1) ? 1 : 0;
    }
    __syncthreads();
    if (last && tid == 0) {
        float inter = 0.f;
        #pragma unroll
        for (int cc = 0; cc < NCHUNK; cc++) inter += g_partial[b][cc];
        float flen = (float)len;
        float dice = (2.0f * inter + 1.0f) / (2.0f * flen + 1.0f);
        out[b] = 1.0f - dice;
        g_arrive[b] = 0;                 // self-reset for the next replay
    }
}

// ---------------------------------------------------------------------------
extern "C" void kernel_launch(void* const* d_in, const int* in_sizes, int n_in,
                              void* d_out, int out_size)
{
    const float* pots    = (const float*)d_in[0];   // [B,T,N] fp32
    const int*   y_true  = (const int*)  d_in[1];   // [B,T] int32
    const int*   lengths = (const int*)  d_in[2];   // [B] int32
    const float* trans   = (const float*)d_in[3];   // [N,N] fp32
    float* out = (float*)d_out;                     // [B] fp32

    fb_kernel<<<NWORK_MAX / WPB, 32 * WPB>>>(pots, lengths, trans);
    combine_kernel<<<dim3(BB, NCHUNK), 256>>>(y_true, lengths, out);
}